// round 12
// baseline (speedup 1.0000x reference)
#include <cuda_runtime.h>
#include <cuda_fp16.h>
#include <cstdint>

// MoeGate: mma.sync m16n8k16 fp16 (3-term split) + exact-fp32 fixup.
// R12: fixup rebuilt as 1 thread per (token,expert) -- critical path drops
// from a 64-chunk serial staged sweep (~40us) to a 2048-FMA chain (~7us);
// loss_kernel widened to 1024 threads. Gate frozen from R11 (canary rel_err
// 2.787343e-06 confirms fragment-plane B path exact).

#define HDIM   2048
#define NEXP   64
#define KTOP   8
#define BM     64
#define KC     32
#define NCHUNK (HDIM / KC)
#define NTHR   128                         // 4 warps: 2M x 2N, 32x32 tile each
#define PH     40                          // A smem pitch in halves
#define STG_HALVES (2 * BM * PH)           // hi+lo planes: 5120 halves = 10KB
#define LG_PITCH 65
#define NBLK   256                         // T / BM
#define FTOK   4
#define FGRID  1024

__device__ float g_pi_part[NBLK * NEXP];
__device__ float g_cnt_part[NBLK * NEXP];
__device__ int   g_flag_cnt = 0;
__device__ int   g_flag_idx[16384];
// W fragment planes: uint4 index = (c*8 + g*4 + r4)*32 + lane
__device__ uint4 g_whi[16384];
__device__ uint4 g_wlo[16384];

__device__ __forceinline__ void mma_f16(float* c, const uint32_t* a, const uint32_t* b) {
    asm volatile(
        "mma.sync.aligned.m16n8k16.row.col.f32.f16.f16.f32 "
        "{%0,%1,%2,%3}, {%4,%5,%6,%7}, {%8,%9}, {%0,%1,%2,%3};"
        : "+f"(c[0]), "+f"(c[1]), "+f"(c[2]), "+f"(c[3])
        : "r"(a[0]), "r"(a[1]), "r"(a[2]), "r"(a[3]), "r"(b[0]), "r"(b[1]));
}

__device__ __forceinline__ void split_h2(float a, float b, uint32_t& hi, uint32_t& lo) {
    __half ha = __float2half_rn(a), hb = __float2half_rn(b);
    float ra = a - __half2float(ha), rb = b - __half2float(hb);
    __half2 h = __halves2half2(ha, hb);
    __half2 l = __halves2half2(__float2half_rn(ra), __float2half_rn(rb));
    hi = *(uint32_t*)&h;
    lo = *(uint32_t*)&l;
}

// One-time W -> fragment-layout fp16 hi/lo planes (mirrors gate's read mapping).
__global__ void prep_w(const float* __restrict__ w) {
    int idx = blockIdx.x * 256 + threadIdx.x;      // uint4 id, 0..16383
    int lane = idx & 31;
    int r4   = (idx >> 5) & 3;
    int g    = (idx >> 7) & 1;
    int c    = idx >> 8;
    int qid  = lane & 3, grp = lane >> 2;
    uint32_t hi4[4], lo4[4];
#pragma unroll
    for (int i = 0; i < 4; i++) {
        int r  = r4 * 4 + i;
        int q  = r >> 3, nt = (r >> 1) & 3, b = r & 1;
        int n  = g * 32 + nt * 8 + grp;
        int k  = c * 32 + 16 * q + 2 * qid + 8 * b;
        split_h2(w[n * HDIM + k], w[n * HDIM + k + 1], hi4[i], lo4[i]);
    }
    g_whi[idx] = make_uint4(hi4[0], hi4[1], hi4[2], hi4[3]);
    g_wlo[idx] = make_uint4(lo4[0], lo4[1], lo4[2], lo4[3]);
}

__global__ __launch_bounds__(NTHR, 3) void gate_kernel(
    const float* __restrict__ x, const float* __restrict__ w,
    float* __restrict__ out, int T, int S)
{
    extern __shared__ char smraw[];
    __half* smemh = (__half*)smraw;
    float*  lg    = (float*)smraw;        // logits overlay after GEMM
    __shared__ float cnt_s[NEXP];

    const int tid  = threadIdx.x;
    const int wid  = tid >> 5;
    const int lane = tid & 31;
    const int grp  = lane >> 2;
    const int qid  = lane & 3;
    const int t0   = blockIdx.x * BM;
    const int mrow0 = (wid & 1) * 32;     // 2 warps in M (32 rows each)
    const int g     = wid >> 1;           // 2 warps in N (32 cols each)
    const int ncol0 = g * 32;

    if (tid < NEXP) cnt_s[tid] = 0.f;

    float acc[2][4][4];
#pragma unroll
    for (int mt = 0; mt < 2; mt++)
#pragma unroll
        for (int nt = 0; nt < 4; nt++)
#pragma unroll
            for (int k = 0; k < 4; k++) acc[mt][nt][k] = 0.f;

    const float* xbase = x + (size_t)t0 * HDIM;
    const uint4* WH = g_whi + g * 128 + lane;
    const uint4* WL = g_wlo + g * 128 + lane;

    float4 rx[4];
    auto ldg_chunk = [&](int c) {
#pragma unroll
        for (int i = 0; i < 4; i++) {
            int id = tid + NTHR * i;
            rx[i] = *(const float4*)(xbase + (size_t)(id >> 3) * HDIM + c * KC + (id & 7) * 4);
        }
    };
    auto sts_chunk = [&](int st) {
        __half* stg = smemh + st * STG_HALVES;
#pragma unroll
        for (int i = 0; i < 4; i++) {
            int id = tid + NTHR * i;
            int idx = (id >> 3) * PH + (id & 7) * 4;
            uint32_t h0, l0, h1, l1;
            split_h2(rx[i].x, rx[i].y, h0, l0);
            split_h2(rx[i].z, rx[i].w, h1, l1);
            *(uint2*)(stg + idx)              = make_uint2(h0, h1);
            *(uint2*)(stg + BM * PH + idx)    = make_uint2(l0, l1);
        }
    };

    ldg_chunk(0);

    for (int c = 0; c < NCHUNK; c++) {
        const int st = c & 1;
        sts_chunk(st);
        __syncthreads();
        if (c + 1 < NCHUNK) ldg_chunk(c + 1);

        uint4 H[4], L[4];
#pragma unroll
        for (int r = 0; r < 4; r++) {
            H[r] = WH[c * 256 + r * 32];
            L[r] = WL[c * 256 + r * 32];
        }

        const __half* stg = smemh + st * STG_HALVES;
        const uint32_t* Ah = (const uint32_t*)stg;
        const uint32_t* Al = (const uint32_t*)(stg + BM * PH);

#pragma unroll
        for (int q = 0; q < 2; q++) {
            const int kb = 8 * q + qid;
            uint32_t ah[2][4], al[2][4];
#pragma unroll
            for (int mt = 0; mt < 2; mt++)
#pragma unroll
                for (int j = 0; j < 4; j++) {
                    int off = (mrow0 + 16 * mt + grp + 8 * (j & 1)) * 20 + kb + 4 * (j >> 1);
                    ah[mt][j] = Ah[off];
                    al[mt][j] = Al[off];
                }
            uint32_t bh[4][2], bl[4][2];
            {
                uint4 h0 = H[2 * q], h1 = H[2 * q + 1];
                uint4 l0 = L[2 * q], l1 = L[2 * q + 1];
                bh[0][0] = h0.x; bh[0][1] = h0.y; bh[1][0] = h0.z; bh[1][1] = h0.w;
                bh[2][0] = h1.x; bh[2][1] = h1.y; bh[3][0] = h1.z; bh[3][1] = h1.w;
                bl[0][0] = l0.x; bl[0][1] = l0.y; bl[1][0] = l0.z; bl[1][1] = l0.w;
                bl[2][0] = l1.x; bl[2][1] = l1.y; bl[3][0] = l1.z; bl[3][1] = l1.w;
            }
#pragma unroll
            for (int nt = 0; nt < 4; nt++)
#pragma unroll
                for (int mt = 0; mt < 2; mt++) mma_f16(acc[mt][nt], ah[mt], bh[nt]);
#pragma unroll
            for (int nt = 0; nt < 4; nt++)
#pragma unroll
                for (int mt = 0; mt < 2; mt++) mma_f16(acc[mt][nt], ah[mt], bl[nt]);
#pragma unroll
            for (int nt = 0; nt < 4; nt++)
#pragma unroll
                for (int mt = 0; mt < 2; mt++) mma_f16(acc[mt][nt], al[mt], bh[nt]);
        }
        __syncthreads();
    }

    // ---- logits -> smem ----
#pragma unroll
    for (int mt = 0; mt < 2; mt++)
#pragma unroll
        for (int nt = 0; nt < 4; nt++) {
            int row = mrow0 + 16 * mt + grp;
            int col = ncol0 + nt * 8 + 2 * qid;
            lg[row * LG_PITCH + col]           = acc[mt][nt][0];
            lg[row * LG_PITCH + col + 1]       = acc[mt][nt][1];
            lg[(row + 8) * LG_PITCH + col]     = acc[mt][nt][2];
            lg[(row + 8) * LG_PITCH + col + 1] = acc[mt][nt][3];
        }
    __syncthreads();

    // ---- per-token epilogue (threads 0..63) ----
    if (tid < BM) {
        float sc[NEXP];
        float mx = -1e30f;
#pragma unroll
        for (int e = 0; e < NEXP; e++) { sc[e] = lg[tid * LG_PITCH + e]; mx = fmaxf(mx, sc[e]); }
        float sum = 0.f;
#pragma unroll
        for (int e = 0; e < NEXP; e++) { sc[e] = __expf(sc[e] - mx); sum += sc[e]; }
        float inv = 1.f / sum;
#pragma unroll
        for (int e = 0; e < NEXP; e++) sc[e] *= inv;
#pragma unroll
        for (int e = 0; e < NEXP; e++) lg[tid * LG_PITCH + e] = sc[e];

        float vsel[KTOP + 1]; int isel[KTOP + 1]; float wsum = 0.f;
#pragma unroll
        for (int j = 0; j < KTOP + 1; j++) {
            float bv = -1.f; int bi = 0;
#pragma unroll
            for (int e = 0; e < NEXP; e++) if (sc[e] > bv) { bv = sc[e]; bi = e; }
            vsel[j] = bv; isel[j] = bi;
#pragma unroll
            for (int e = 0; e < NEXP; e++) if (e == bi) sc[e] = -1.f;
            if (j < KTOP) { wsum += bv; atomicAdd(&cnt_s[bi], 1.f); }
        }
        bool flag = false;
#pragma unroll
        for (int j = 0; j < KTOP; j++)
            if (vsel[j] - vsel[j + 1] < vsel[j] * 1e-3f + 2e-6f) flag = true;

        size_t t = (size_t)t0 + tid;
        if (flag) {
            int p = atomicAdd(&g_flag_cnt, 1);
            g_flag_idx[p] = (int)t;
        }
        float rn = 1.f / (wsum + 1e-20f);
#pragma unroll
        for (int j = 0; j < KTOP; j++) {
            out[t * KTOP + j] = (float)isel[j];
            out[(size_t)T * KTOP + t * KTOP + j] = vsel[j] * rn;
        }
    }
    __syncthreads();

    if (tid < NEXP) {
        float pe = 0.f;
#pragma unroll 8
        for (int m = 0; m < BM; m++) pe += lg[m * LG_PITCH + tid];
        g_pi_part[blockIdx.x * NEXP + tid]  = pe;
        g_cnt_part[blockIdx.x * NEXP + tid] = cnt_s[tid];
    }
}

// Exact-fp32 fixup: ONE THREAD per (token, expert); full k=0..2047 sequential
// fma chain per thread (R1-proven order). Critical path = 2048 dependent FMAs
// (~8k cyc) instead of a 64-chunk staged CTA sweep. W double-buffered in
// pitch-33 smem (conflict-free); x via lane-uniform broadcast LDG.
__global__ __launch_bounds__(256) void fixup_kernel(
    const float* __restrict__ x, const float* __restrict__ w,
    float* __restrict__ out, int T)
{
    __shared__ float ws[2][64 * 33];      // [stage][e*33 + k]
    __shared__ float lgs[FTOK][68];

    const int tid = threadIdx.x;
    const int e   = tid & 63;
    const int t   = tid >> 6;             // 0..3
    const int nflag = g_flag_cnt;

    const int wrow0 = tid >> 3;           // W stage: float4 id=tid(+256)
    const int wrow1 = (tid + 256) >> 3;
    const int wseg  = tid & 7;
    const int k0s   = wseg * 4;

    for (int base = blockIdx.x * FTOK; base < nflag; base += FGRID * FTOK) {
        int fi = g_flag_idx[(base + t < nflag) ? (base + t) : base];
        const float4* xr = (const float4*)(x + (size_t)fi * HDIM);

        float4 pw0 = *(const float4*)(w + (size_t)wrow0 * HDIM + k0s);
        float4 pw1 = *(const float4*)(w + (size_t)wrow1 * HDIM + k0s);
        {
            float* b = ws[0];
            b[wrow0 * 33 + k0s]     = pw0.x; b[wrow0 * 33 + k0s + 1] = pw0.y;
            b[wrow0 * 33 + k0s + 2] = pw0.z; b[wrow0 * 33 + k0s + 3] = pw0.w;
            b[wrow1 * 33 + k0s]     = pw1.x; b[wrow1 * 33 + k0s + 1] = pw1.y;
            b[wrow1 * 33 + k0s + 2] = pw1.z; b[wrow1 * 33 + k0s + 3] = pw1.w;
        }
        __syncthreads();

        float acc = 0.f;
        for (int c = 0; c < 64; c++) {
            if (c < 63) {
                pw0 = *(const float4*)(w + (size_t)wrow0 * HDIM + (c + 1) * 32 + k0s);
                pw1 = *(const float4*)(w + (size_t)wrow1 * HDIM + (c + 1) * 32 + k0s);
            }
            const float* we = ws[c & 1] + e * 33;
#pragma unroll
            for (int i = 0; i < 8; i++) {
                float4 xv = xr[c * 8 + i];          // lane-uniform -> broadcast
                acc = fmaf(xv.x, we[i * 4],     acc);
                acc = fmaf(xv.y, we[i * 4 + 1], acc);
                acc = fmaf(xv.z, we[i * 4 + 2], acc);
                acc = fmaf(xv.w, we[i * 4 + 3], acc);
            }
            if (c < 63) {
                float* nb = ws[(c + 1) & 1];
                nb[wrow0 * 33 + k0s]     = pw0.x; nb[wrow0 * 33 + k0s + 1] = pw0.y;
                nb[wrow0 * 33 + k0s + 2] = pw0.z; nb[wrow0 * 33 + k0s + 3] = pw0.w;
                nb[wrow1 * 33 + k0s]     = pw1.x; nb[wrow1 * 33 + k0s + 1] = pw1.y;
                nb[wrow1 * 33 + k0s + 2] = pw1.z; nb[wrow1 * 33 + k0s + 3] = pw1.w;
                __syncthreads();
            }
        }
        lgs[t][e] = acc;
        __syncthreads();

        if (e == 0 && base + t < nflag) {
            int tok = g_flag_idx[base + t];
            float sc[NEXP];
            float mx = -1e30f;
#pragma unroll
            for (int j = 0; j < NEXP; j++) { sc[j] = lgs[t][j]; mx = fmaxf(mx, sc[j]); }
            float sum = 0.f;
#pragma unroll
            for (int j = 0; j < NEXP; j++) { sc[j] = __expf(sc[j] - mx); sum += sc[j]; }
            float inv = 1.f / sum;
#pragma unroll
            for (int j = 0; j < NEXP; j++) sc[j] *= inv;

            float wsel[KTOP]; int isel[KTOP]; float wsum = 0.f;
#pragma unroll
            for (int j = 0; j < KTOP; j++) {
                float bv = -1.f; int bi = 0;
#pragma unroll
                for (int e2 = 0; e2 < NEXP; e2++) if (sc[e2] > bv) { bv = sc[e2]; bi = e2; }
                wsel[j] = bv; isel[j] = bi; wsum += bv;
                sc[bi] = -1.f;
            }
            float rn = 1.f / (wsum + 1e-20f);
#pragma unroll
            for (int j = 0; j < KTOP; j++) {
                out[(size_t)tok * KTOP + j] = (float)isel[j];
                out[(size_t)T * KTOP + (size_t)tok * KTOP + j] = wsel[j] * rn;
            }
        }
        __syncthreads();
    }
}

__global__ void loss_kernel(float* __restrict__ out, int T, int S, int B) {
    __shared__ float sp[1024], sq[1024], red[256];
    int tid = threadIdx.x;
    if (tid == 0) g_flag_cnt = 0;            // reset for next graph replay
    int pair = tid >> 2;                     // (b,e) 0..255
    int part = tid & 3;
    int e = pair & 63, b = pair >> 6;
    float ps = 0.f, cs = 0.f;
    int blk0 = b * (NBLK / 4) + part * (NBLK / 16);
    for (int blk = blk0; blk < blk0 + NBLK / 16; blk++) {
        ps += g_pi_part[blk * NEXP + e];
        cs += g_cnt_part[blk * NEXP + e];
    }
    sp[tid] = ps; sq[tid] = cs;
    __syncthreads();
    if (tid < 256) {
        float P = sp[4 * tid] + sp[4 * tid + 1] + sp[4 * tid + 2] + sp[4 * tid + 3];
        float C = sq[4 * tid] + sq[4 * tid + 1] + sq[4 * tid + 2] + sq[4 * tid + 3];
        float pi = P / (float)S;
        float fi = C * ((float)NEXP / (float)(S * KTOP));
        red[tid] = pi * fi;
    }
    __syncthreads();
    for (int s = 128; s > 0; s >>= 1) {
        if (tid < s) red[tid] += red[tid + s];
        __syncthreads();
    }
    if (tid == 0)
        out[(size_t)2 * T * KTOP] = red[0] * 0.01f / (float)B;
}

extern "C" void kernel_launch(void* const* d_in, const int* in_sizes, int n_in,
                              void* d_out, int out_size)
{
    const float* x = (const float*)d_in[0];
    const float* w = (const float*)d_in[1];
    float* out = (float*)d_out;

    int Hrt = in_sizes[1] / NEXP;    // 2048
    int T   = in_sizes[0] / Hrt;     // 16384
    int B   = 4;
    int S   = T / B;                 // 4096

    size_t smem_bytes = 2 * STG_HALVES * sizeof(__half);   // 20480
    cudaFuncSetAttribute(gate_kernel, cudaFuncAttributeMaxDynamicSharedMemorySize,
                         (int)smem_bytes);

    prep_w<<<64, 256>>>(w);
    gate_kernel<<<T / BM, NTHR, smem_bytes>>>(x, w, out, T, S);
    fixup_kernel<<<FGRID, 256>>>(x, w, out, T);
    loss_kernel<<<1, 1024>>>(out, T, S, B);
}

// round 13
// speedup vs baseline: 1.2522x; 1.2522x over previous
#include <cuda_runtime.h>
#include <cuda_fp16.h>
#include <cstdint>

// MoeGate: mma.sync m16n8k16 fp16 (3-term split) + exact-fp32 fixup.
// R13: gate mainloop has NO smem and NO syncthreads -- A fragments are
// per-thread-private in the m16n8k16 layout, so each thread LDGs its own
// fp32 pairs straight from x and splits in-register; B comes from the
// R11-proven fragment-layout hi/lo planes. DRAM (x read once) becomes the
// binding roof (~21us). Fixup/loss reverted to R11-best configs (R12's
// per-thread-chain fixup exploded W L2 traffic: 151.7 -> 205.8).

#define HDIM   2048
#define NEXP   64
#define KTOP   8
#define BM     64
#define KC     32
#define NCHUNK (HDIM / KC)
#define NTHR   128                         // 4 warps: 2M x 2N, 32x32 tile each
#define LG_PITCH 65
#define NBLK   256                         // T / BM
#define FTOK   32
#define FGRID  148

__device__ float g_pi_part[NBLK * NEXP];
__device__ float g_cnt_part[NBLK * NEXP];
__device__ int   g_flag_cnt = 0;
__device__ int   g_flag_idx[16384];
// W fragment planes: uint4 index = (c*8 + g*4 + r4)*32 + lane
__device__ uint4 g_whi[16384];
__device__ uint4 g_wlo[16384];

__device__ __forceinline__ void mma_f16(float* c, const uint32_t* a, const uint32_t* b) {
    asm volatile(
        "mma.sync.aligned.m16n8k16.row.col.f32.f16.f16.f32 "
        "{%0,%1,%2,%3}, {%4,%5,%6,%7}, {%8,%9}, {%0,%1,%2,%3};"
        : "+f"(c[0]), "+f"(c[1]), "+f"(c[2]), "+f"(c[3])
        : "r"(a[0]), "r"(a[1]), "r"(a[2]), "r"(a[3]), "r"(b[0]), "r"(b[1]));
}

__device__ __forceinline__ void split_h2(float a, float b, uint32_t& hi, uint32_t& lo) {
    __half ha = __float2half_rn(a), hb = __float2half_rn(b);
    float ra = a - __half2float(ha), rb = b - __half2float(hb);
    __half2 h = __halves2half2(ha, hb);
    __half2 l = __halves2half2(__float2half_rn(ra), __float2half_rn(rb));
    hi = *(uint32_t*)&h;
    lo = *(uint32_t*)&l;
}

// One-time W -> fragment-layout fp16 hi/lo planes (mirrors gate's read mapping).
__global__ void prep_w(const float* __restrict__ w) {
    int idx = blockIdx.x * 256 + threadIdx.x;      // uint4 id, 0..16383
    int lane = idx & 31;
    int r4   = (idx >> 5) & 3;
    int g    = (idx >> 7) & 1;
    int c    = idx >> 8;
    int qid  = lane & 3, grp = lane >> 2;
    uint32_t hi4[4], lo4[4];
#pragma unroll
    for (int i = 0; i < 4; i++) {
        int r  = r4 * 4 + i;
        int q  = r >> 3, nt = (r >> 1) & 3, b = r & 1;
        int n  = g * 32 + nt * 8 + grp;
        int k  = c * 32 + 16 * q + 2 * qid + 8 * b;
        split_h2(w[n * HDIM + k], w[n * HDIM + k + 1], hi4[i], lo4[i]);
    }
    g_whi[idx] = make_uint4(hi4[0], hi4[1], hi4[2], hi4[3]);
    g_wlo[idx] = make_uint4(lo4[0], lo4[1], lo4[2], lo4[3]);
}

__global__ __launch_bounds__(NTHR, 2) void gate_kernel(
    const float* __restrict__ x, const float* __restrict__ w,
    float* __restrict__ out, int T, int S)
{
    __shared__ float lg[BM * LG_PITCH];   // logits (epilogue only)
    __shared__ float cnt_s[NEXP];

    const int tid  = threadIdx.x;
    const int wid  = tid >> 5;
    const int lane = tid & 31;
    const int grp  = lane >> 2;
    const int qid  = lane & 3;
    const int t0   = blockIdx.x * BM;
    const int mrow0 = (wid & 1) * 32;     // 2 warps in M (32 rows each)
    const int g     = wid >> 1;           // 2 warps in N (32 cols each)
    const int ncol0 = g * 32;

    if (tid < NEXP) cnt_s[tid] = 0.f;

    float acc[2][4][4];
#pragma unroll
    for (int mt = 0; mt < 2; mt++)
#pragma unroll
        for (int nt = 0; nt < 4; nt++)
#pragma unroll
            for (int k = 0; k < 4; k++) acc[mt][nt][k] = 0.f;

    const uint4* WH = g_whi + g * 128 + lane;
    const uint4* WL = g_wlo + g * 128 + lane;

    // Per-thread A row pointers (fragment rows), pre-offset by 2*qid.
    const float* rp[2][2];
#pragma unroll
    for (int mt = 0; mt < 2; mt++)
#pragma unroll
        for (int jr = 0; jr < 2; jr++)
            rp[mt][jr] = x + (size_t)(t0 + mrow0 + 16 * mt + grp + 8 * jr) * HDIM + 2 * qid;

    // Raw A pairs for one chunk: xr[mt][q][j], j&1 = row+8 sel, j>>1 = k+8 sel
    float2 xr[2][2][4];
    auto ldgA = [&](int c) {
#pragma unroll
        for (int mt = 0; mt < 2; mt++)
#pragma unroll
            for (int q = 0; q < 2; q++)
#pragma unroll
                for (int j = 0; j < 4; j++)
                    xr[mt][q][j] = *(const float2*)(rp[mt][j & 1] + c * 32 + 16 * q + 8 * (j >> 1));
    };

    ldgA(0);

    for (int c = 0; c < NCHUNK; c++) {
        // split current A in-register (identical arithmetic to R11's producer split)
        uint32_t ah[2][2][4], al[2][2][4];
#pragma unroll
        for (int mt = 0; mt < 2; mt++)
#pragma unroll
            for (int q = 0; q < 2; q++)
#pragma unroll
                for (int j = 0; j < 4; j++)
                    split_h2(xr[mt][q][j].x, xr[mt][q][j].y, ah[mt][q][j], al[mt][q][j]);

        uint4 H[4], L[4];
#pragma unroll
        for (int r = 0; r < 4; r++) {
            H[r] = WH[c * 256 + r * 32];
            L[r] = WL[c * 256 + r * 32];
        }

        if (c + 1 < NCHUNK) ldgA(c + 1);   // xr already consumed into ah/al

#pragma unroll
        for (int q = 0; q < 2; q++) {
            uint32_t bh[4][2], bl[4][2];
            {
                uint4 h0 = H[2 * q], h1 = H[2 * q + 1];
                uint4 l0 = L[2 * q], l1 = L[2 * q + 1];
                bh[0][0] = h0.x; bh[0][1] = h0.y; bh[1][0] = h0.z; bh[1][1] = h0.w;
                bh[2][0] = h1.x; bh[2][1] = h1.y; bh[3][0] = h1.z; bh[3][1] = h1.w;
                bl[0][0] = l0.x; bl[0][1] = l0.y; bl[1][0] = l0.z; bl[1][1] = l0.w;
                bl[2][0] = l1.x; bl[2][1] = l1.y; bl[3][0] = l1.z; bl[3][1] = l1.w;
            }
            // same per-(m,n) sequence as R11: q0 hh,hl,lh then q1 hh,hl,lh
#pragma unroll
            for (int nt = 0; nt < 4; nt++)
#pragma unroll
                for (int mt = 0; mt < 2; mt++) mma_f16(acc[mt][nt], ah[mt][q], bh[nt]);
#pragma unroll
            for (int nt = 0; nt < 4; nt++)
#pragma unroll
                for (int mt = 0; mt < 2; mt++) mma_f16(acc[mt][nt], ah[mt][q], bl[nt]);
#pragma unroll
            for (int nt = 0; nt < 4; nt++)
#pragma unroll
                for (int mt = 0; mt < 2; mt++) mma_f16(acc[mt][nt], al[mt][q], bh[nt]);
        }
    }

    // ---- logits -> smem ----
#pragma unroll
    for (int mt = 0; mt < 2; mt++)
#pragma unroll
        for (int nt = 0; nt < 4; nt++) {
            int row = mrow0 + 16 * mt + grp;
            int col = ncol0 + nt * 8 + 2 * qid;
            lg[row * LG_PITCH + col]           = acc[mt][nt][0];
            lg[row * LG_PITCH + col + 1]       = acc[mt][nt][1];
            lg[(row + 8) * LG_PITCH + col]     = acc[mt][nt][2];
            lg[(row + 8) * LG_PITCH + col + 1] = acc[mt][nt][3];
        }
    __syncthreads();

    // ---- per-token epilogue (threads 0..63) ----
    if (tid < BM) {
        float sc[NEXP];
        float mx = -1e30f;
#pragma unroll
        for (int e = 0; e < NEXP; e++) { sc[e] = lg[tid * LG_PITCH + e]; mx = fmaxf(mx, sc[e]); }
        float sum = 0.f;
#pragma unroll
        for (int e = 0; e < NEXP; e++) { sc[e] = __expf(sc[e] - mx); sum += sc[e]; }
        float inv = 1.f / sum;
#pragma unroll
        for (int e = 0; e < NEXP; e++) sc[e] *= inv;
#pragma unroll
        for (int e = 0; e < NEXP; e++) lg[tid * LG_PITCH + e] = sc[e];

        float vsel[KTOP + 1]; int isel[KTOP + 1]; float wsum = 0.f;
#pragma unroll
        for (int j = 0; j < KTOP + 1; j++) {
            float bv = -1.f; int bi = 0;
#pragma unroll
            for (int e = 0; e < NEXP; e++) if (sc[e] > bv) { bv = sc[e]; bi = e; }
            vsel[j] = bv; isel[j] = bi;
#pragma unroll
            for (int e = 0; e < NEXP; e++) if (e == bi) sc[e] = -1.f;
            if (j < KTOP) { wsum += bv; atomicAdd(&cnt_s[bi], 1.f); }
        }
        bool flag = false;
#pragma unroll
        for (int j = 0; j < KTOP; j++)
            if (vsel[j] - vsel[j + 1] < vsel[j] * 1e-3f + 2e-6f) flag = true;

        size_t t = (size_t)t0 + tid;
        if (flag) {
            int p = atomicAdd(&g_flag_cnt, 1);
            g_flag_idx[p] = (int)t;
        }
        float rn = 1.f / (wsum + 1e-20f);
#pragma unroll
        for (int j = 0; j < KTOP; j++) {
            out[t * KTOP + j] = (float)isel[j];
            out[(size_t)T * KTOP + t * KTOP + j] = vsel[j] * rn;
        }
    }
    __syncthreads();

    if (tid < NEXP) {
        float pe = 0.f;
#pragma unroll 8
        for (int m = 0; m < BM; m++) pe += lg[m * LG_PITCH + tid];
        g_pi_part[blockIdx.x * NEXP + tid]  = pe;
        g_cnt_part[blockIdx.x * NEXP + tid] = cnt_s[tid];
    }
}

// Exact-fp32 fixup (R11-best config): sequential-k fma chain per (token,
// expert), FTOK=32 amortizes W reads, 148 CTAs. R1-proven arithmetic order.
__global__ __launch_bounds__(256) void fixup_kernel(
    const float* __restrict__ x, const float* __restrict__ w,
    float* __restrict__ out, int T)
{
    __shared__ float4 ws4[8 * 66];
    __shared__ float4 xs4[FTOK * 9];
    __shared__ float  lgs[FTOK][72];

    const int tid = threadIdx.x;
    const int e   = tid & 63;
    const int tp  = tid >> 6;
    const int nflag = g_flag_cnt;

    const int wr0 = tid >> 3,        wq = tid & 7;
    const int wr1 = (tid + 256) >> 3;
    const int xt  = tid >> 3,        xq = tid & 7;

    for (int base = blockIdx.x * FTOK; base < nflag; base += FGRID * FTOK) {
        float acc[8];
#pragma unroll
        for (int u = 0; u < 8; u++) acc[u] = 0.f;

        int fi = (base + xt < nflag) ? g_flag_idx[base + xt] : g_flag_idx[base];

        float4 pw0 = *(const float4*)(w + (size_t)wr0 * HDIM + wq * 4);
        float4 pw1 = *(const float4*)(w + (size_t)wr1 * HDIM + wq * 4);
        float4 px  = *(const float4*)(x + (size_t)fi * HDIM + xq * 4);

        for (int c = 0; c < 64; c++) {
            ws4[wq * 66 + wr0] = pw0;
            ws4[wq * 66 + wr1] = pw1;
            xs4[xt * 9 + xq]   = px;
            __syncthreads();

            if (c < 63) {
                pw0 = *(const float4*)(w + (size_t)wr0 * HDIM + (c + 1) * 32 + wq * 4);
                pw1 = *(const float4*)(w + (size_t)wr1 * HDIM + (c + 1) * 32 + wq * 4);
                px  = *(const float4*)(x + (size_t)fi * HDIM + (c + 1) * 32 + xq * 4);
            }
#pragma unroll
            for (int kq = 0; kq < 8; kq++) {
                float4 wv = ws4[kq * 66 + e];
#pragma unroll
                for (int u = 0; u < 8; u++) {
                    float4 xv = xs4[(8 * tp + u) * 9 + kq];
                    acc[u] = fmaf(xv.x, wv.x, acc[u]);
                    acc[u] = fmaf(xv.y, wv.y, acc[u]);
                    acc[u] = fmaf(xv.z, wv.z, acc[u]);
                    acc[u] = fmaf(xv.w, wv.w, acc[u]);
                }
            }
            __syncthreads();
        }

#pragma unroll
        for (int u = 0; u < 8; u++) lgs[8 * tp + u][e] = acc[u];
        __syncthreads();

        if (tid < FTOK && base + tid < nflag) {
            int t = g_flag_idx[base + tid];
            float sc[NEXP];
            float mx = -1e30f;
#pragma unroll
            for (int j = 0; j < NEXP; j++) { sc[j] = lgs[tid][j]; mx = fmaxf(mx, sc[j]); }
            float sum = 0.f;
#pragma unroll
            for (int j = 0; j < NEXP; j++) { sc[j] = __expf(sc[j] - mx); sum += sc[j]; }
            float inv = 1.f / sum;
#pragma unroll
            for (int j = 0; j < NEXP; j++) sc[j] *= inv;

            float wsel[KTOP]; int isel[KTOP]; float wsum = 0.f;
#pragma unroll
            for (int j = 0; j < KTOP; j++) {
                float bv = -1.f; int bi = 0;
#pragma unroll
                for (int e2 = 0; e2 < NEXP; e2++) if (sc[e2] > bv) { bv = sc[e2]; bi = e2; }
                wsel[j] = bv; isel[j] = bi; wsum += bv;
                sc[bi] = -1.f;
            }
            float rn = 1.f / (wsum + 1e-20f);
#pragma unroll
            for (int j = 0; j < KTOP; j++) {
                out[(size_t)t * KTOP + j] = (float)isel[j];
                out[(size_t)T * KTOP + (size_t)t * KTOP + j] = wsel[j] * rn;
            }
        }
        __syncthreads();
    }
}

__global__ void loss_kernel(float* __restrict__ out, int T, int S, int B) {
    __shared__ float sp[1024], sq[1024], red[256];
    int tid = threadIdx.x;
    if (tid == 0) g_flag_cnt = 0;            // reset for next graph replay
    int pair = tid >> 2;                     // (b,e) 0..255
    int part = tid & 3;
    int e = pair & 63, b = pair >> 6;
    float ps = 0.f, cs = 0.f;
    int blk0 = b * (NBLK / 4) + part * (NBLK / 16);
    for (int blk = blk0; blk < blk0 + NBLK / 16; blk++) {
        ps += g_pi_part[blk * NEXP + e];
        cs += g_cnt_part[blk * NEXP + e];
    }
    sp[tid] = ps; sq[tid] = cs;
    __syncthreads();
    if (tid < 256) {
        float P = sp[4 * tid] + sp[4 * tid + 1] + sp[4 * tid + 2] + sp[4 * tid + 3];
        float C = sq[4 * tid] + sq[4 * tid + 1] + sq[4 * tid + 2] + sq[4 * tid + 3];
        float pi = P / (float)S;
        float fi = C * ((float)NEXP / (float)(S * KTOP));
        red[tid] = pi * fi;
    }
    __syncthreads();
    for (int s = 128; s > 0; s >>= 1) {
        if (tid < s) red[tid] += red[tid + s];
        __syncthreads();
    }
    if (tid == 0)
        out[(size_t)2 * T * KTOP] = red[0] * 0.01f / (float)B;
}

extern "C" void kernel_launch(void* const* d_in, const int* in_sizes, int n_in,
                              void* d_out, int out_size)
{
    const float* x = (const float*)d_in[0];
    const float* w = (const float*)d_in[1];
    float* out = (float*)d_out;

    int Hrt = in_sizes[1] / NEXP;    // 2048
    int T   = in_sizes[0] / Hrt;     // 16384
    int B   = 4;
    int S   = T / B;                 // 4096

    prep_w<<<64, 256>>>(w);
    gate_kernel<<<T / BM, NTHR>>>(x, w, out, T, S);
    fixup_kernel<<<FGRID, 256>>>(x, w, out, T);
    loss_kernel<<<1, 1024>>>(out, T, S, B);
}

// round 14
// speedup vs baseline: 1.2690x; 1.0134x over previous
#include <cuda_runtime.h>
#include <cuda_fp16.h>
#include <cstdint>

// MoeGate: mma.sync m16n8k16 fp16 (3-term split) + exact-fp32 fixup.
// R14: gate restored VERBATIM to R11 (best measured: 151.7 total; R13's
// smem-free variant regressed 12.6us). Tail restructured: fixup FTOK 32->16
// halves the per-CTA serial sweep wall (~40->~25us, the dominant non-gate
// cost); loss folded into fixup's last CTA (saves the 8.5us serialized
// launch); g_flag_cnt reset moved to prep_w (pre-gate, race-free).

#define HDIM   2048
#define NEXP   64
#define KTOP   8
#define BM     64
#define KC     32
#define NCHUNK (HDIM / KC)
#define NTHR   128                         // 4 warps: 2M x 2N, 32x32 tile each
#define PH     40                          // A smem pitch in halves
#define STG_HALVES (2 * BM * PH)           // hi+lo planes: 5120 halves = 10KB
#define LG_PITCH 65
#define NBLK   256                         // T / BM
#define FTOK   16
#define FGRID  296

__device__ float g_pi_part[NBLK * NEXP];
__device__ float g_cnt_part[NBLK * NEXP];
__device__ int   g_flag_cnt = 0;
__device__ int   g_flag_idx[16384];
// W fragment planes: uint4 index = (c*8 + g*4 + r4)*32 + lane
__device__ uint4 g_whi[16384];
__device__ uint4 g_wlo[16384];

__device__ __forceinline__ void mma_f16(float* c, const uint32_t* a, const uint32_t* b) {
    asm volatile(
        "mma.sync.aligned.m16n8k16.row.col.f32.f16.f16.f32 "
        "{%0,%1,%2,%3}, {%4,%5,%6,%7}, {%8,%9}, {%0,%1,%2,%3};"
        : "+f"(c[0]), "+f"(c[1]), "+f"(c[2]), "+f"(c[3])
        : "r"(a[0]), "r"(a[1]), "r"(a[2]), "r"(a[3]), "r"(b[0]), "r"(b[1]));
}

__device__ __forceinline__ void split_h2(float a, float b, uint32_t& hi, uint32_t& lo) {
    __half ha = __float2half_rn(a), hb = __float2half_rn(b);
    float ra = a - __half2float(ha), rb = b - __half2float(hb);
    __half2 h = __halves2half2(ha, hb);
    __half2 l = __halves2half2(__float2half_rn(ra), __float2half_rn(rb));
    hi = *(uint32_t*)&h;
    lo = *(uint32_t*)&l;
}

// One-time W -> fragment-layout fp16 hi/lo planes. Also resets the flag
// counter (runs before gate writes flags on every replay).
__global__ void prep_w(const float* __restrict__ w) {
    if (blockIdx.x == 0 && threadIdx.x == 0) g_flag_cnt = 0;
    int idx = blockIdx.x * 256 + threadIdx.x;      // uint4 id, 0..16383
    int lane = idx & 31;
    int r4   = (idx >> 5) & 3;
    int g    = (idx >> 7) & 1;
    int c    = idx >> 8;
    int qid  = lane & 3, grp = lane >> 2;
    uint32_t hi4[4], lo4[4];
#pragma unroll
    for (int i = 0; i < 4; i++) {
        int r  = r4 * 4 + i;
        int q  = r >> 3, nt = (r >> 1) & 3, b = r & 1;
        int n  = g * 32 + nt * 8 + grp;
        int k  = c * 32 + 16 * q + 2 * qid + 8 * b;
        split_h2(w[n * HDIM + k], w[n * HDIM + k + 1], hi4[i], lo4[i]);
    }
    g_whi[idx] = make_uint4(hi4[0], hi4[1], hi4[2], hi4[3]);
    g_wlo[idx] = make_uint4(lo4[0], lo4[1], lo4[2], lo4[3]);
}

__global__ __launch_bounds__(NTHR, 3) void gate_kernel(
    const float* __restrict__ x, const float* __restrict__ w,
    float* __restrict__ out, int T, int S)
{
    extern __shared__ char smraw[];
    __half* smemh = (__half*)smraw;
    float*  lg    = (float*)smraw;        // logits overlay after GEMM
    __shared__ float cnt_s[NEXP];

    const int tid  = threadIdx.x;
    const int wid  = tid >> 5;
    const int lane = tid & 31;
    const int grp  = lane >> 2;
    const int qid  = lane & 3;
    const int t0   = blockIdx.x * BM;
    const int mrow0 = (wid & 1) * 32;     // 2 warps in M (32 rows each)
    const int g     = wid >> 1;           // 2 warps in N (32 cols each)
    const int ncol0 = g * 32;

    if (tid < NEXP) cnt_s[tid] = 0.f;

    float acc[2][4][4];
#pragma unroll
    for (int mt = 0; mt < 2; mt++)
#pragma unroll
        for (int nt = 0; nt < 4; nt++)
#pragma unroll
            for (int k = 0; k < 4; k++) acc[mt][nt][k] = 0.f;

    const float* xbase = x + (size_t)t0 * HDIM;
    const uint4* WH = g_whi + g * 128 + lane;
    const uint4* WL = g_wlo + g * 128 + lane;

    float4 rx[4];
    auto ldg_chunk = [&](int c) {
#pragma unroll
        for (int i = 0; i < 4; i++) {
            int id = tid + NTHR * i;
            rx[i] = *(const float4*)(xbase + (size_t)(id >> 3) * HDIM + c * KC + (id & 7) * 4);
        }
    };
    auto sts_chunk = [&](int st) {
        __half* stg = smemh + st * STG_HALVES;
#pragma unroll
        for (int i = 0; i < 4; i++) {
            int id = tid + NTHR * i;
            int idx = (id >> 3) * PH + (id & 7) * 4;
            uint32_t h0, l0, h1, l1;
            split_h2(rx[i].x, rx[i].y, h0, l0);
            split_h2(rx[i].z, rx[i].w, h1, l1);
            *(uint2*)(stg + idx)              = make_uint2(h0, h1);
            *(uint2*)(stg + BM * PH + idx)    = make_uint2(l0, l1);
        }
    };

    ldg_chunk(0);

    for (int c = 0; c < NCHUNK; c++) {
        const int st = c & 1;
        sts_chunk(st);
        __syncthreads();
        if (c + 1 < NCHUNK) ldg_chunk(c + 1);

        uint4 H[4], L[4];
#pragma unroll
        for (int r = 0; r < 4; r++) {
            H[r] = WH[c * 256 + r * 32];
            L[r] = WL[c * 256 + r * 32];
        }

        const __half* stg = smemh + st * STG_HALVES;
        const uint32_t* Ah = (const uint32_t*)stg;
        const uint32_t* Al = (const uint32_t*)(stg + BM * PH);

#pragma unroll
        for (int q = 0; q < 2; q++) {
            const int kb = 8 * q + qid;
            uint32_t ah[2][4], al[2][4];
#pragma unroll
            for (int mt = 0; mt < 2; mt++)
#pragma unroll
                for (int j = 0; j < 4; j++) {
                    int off = (mrow0 + 16 * mt + grp + 8 * (j & 1)) * 20 + kb + 4 * (j >> 1);
                    ah[mt][j] = Ah[off];
                    al[mt][j] = Al[off];
                }
            uint32_t bh[4][2], bl[4][2];
            {
                uint4 h0 = H[2 * q], h1 = H[2 * q + 1];
                uint4 l0 = L[2 * q], l1 = L[2 * q + 1];
                bh[0][0] = h0.x; bh[0][1] = h0.y; bh[1][0] = h0.z; bh[1][1] = h0.w;
                bh[2][0] = h1.x; bh[2][1] = h1.y; bh[3][0] = h1.z; bh[3][1] = h1.w;
                bl[0][0] = l0.x; bl[0][1] = l0.y; bl[1][0] = l0.z; bl[1][1] = l0.w;
                bl[2][0] = l1.x; bl[2][1] = l1.y; bl[3][0] = l1.z; bl[3][1] = l1.w;
            }
#pragma unroll
            for (int nt = 0; nt < 4; nt++)
#pragma unroll
                for (int mt = 0; mt < 2; mt++) mma_f16(acc[mt][nt], ah[mt], bh[nt]);
#pragma unroll
            for (int nt = 0; nt < 4; nt++)
#pragma unroll
                for (int mt = 0; mt < 2; mt++) mma_f16(acc[mt][nt], ah[mt], bl[nt]);
#pragma unroll
            for (int nt = 0; nt < 4; nt++)
#pragma unroll
                for (int mt = 0; mt < 2; mt++) mma_f16(acc[mt][nt], al[mt], bh[nt]);
        }
        __syncthreads();
    }

    // ---- logits -> smem ----
#pragma unroll
    for (int mt = 0; mt < 2; mt++)
#pragma unroll
        for (int nt = 0; nt < 4; nt++) {
            int row = mrow0 + 16 * mt + grp;
            int col = ncol0 + nt * 8 + 2 * qid;
            lg[row * LG_PITCH + col]           = acc[mt][nt][0];
            lg[row * LG_PITCH + col + 1]       = acc[mt][nt][1];
            lg[(row + 8) * LG_PITCH + col]     = acc[mt][nt][2];
            lg[(row + 8) * LG_PITCH + col + 1] = acc[mt][nt][3];
        }
    __syncthreads();

    // ---- per-token epilogue (threads 0..63) ----
    if (tid < BM) {
        float sc[NEXP];
        float mx = -1e30f;
#pragma unroll
        for (int e = 0; e < NEXP; e++) { sc[e] = lg[tid * LG_PITCH + e]; mx = fmaxf(mx, sc[e]); }
        float sum = 0.f;
#pragma unroll
        for (int e = 0; e < NEXP; e++) { sc[e] = __expf(sc[e] - mx); sum += sc[e]; }
        float inv = 1.f / sum;
#pragma unroll
        for (int e = 0; e < NEXP; e++) sc[e] *= inv;
#pragma unroll
        for (int e = 0; e < NEXP; e++) lg[tid * LG_PITCH + e] = sc[e];

        float vsel[KTOP + 1]; int isel[KTOP + 1]; float wsum = 0.f;
#pragma unroll
        for (int j = 0; j < KTOP + 1; j++) {
            float bv = -1.f; int bi = 0;
#pragma unroll
            for (int e = 0; e < NEXP; e++) if (sc[e] > bv) { bv = sc[e]; bi = e; }
            vsel[j] = bv; isel[j] = bi;
#pragma unroll
            for (int e = 0; e < NEXP; e++) if (e == bi) sc[e] = -1.f;
            if (j < KTOP) { wsum += bv; atomicAdd(&cnt_s[bi], 1.f); }
        }
        bool flag = false;
#pragma unroll
        for (int j = 0; j < KTOP; j++)
            if (vsel[j] - vsel[j + 1] < vsel[j] * 1e-3f + 2e-6f) flag = true;

        size_t t = (size_t)t0 + tid;
        if (flag) {
            int p = atomicAdd(&g_flag_cnt, 1);
            g_flag_idx[p] = (int)t;
        }
        float rn = 1.f / (wsum + 1e-20f);
#pragma unroll
        for (int j = 0; j < KTOP; j++) {
            out[t * KTOP + j] = (float)isel[j];
            out[(size_t)T * KTOP + t * KTOP + j] = vsel[j] * rn;
        }
    }
    __syncthreads();

    if (tid < NEXP) {
        float pe = 0.f;
#pragma unroll 8
        for (int m = 0; m < BM; m++) pe += lg[m * LG_PITCH + tid];
        g_pi_part[blockIdx.x * NEXP + tid]  = pe;
        g_cnt_part[blockIdx.x * NEXP + tid] = cnt_s[tid];
    }
}

// Exact-fp32 fixup (sequential-k fma chain, R1-proven order) + fused loss.
// FTOK=16: per-CTA serial sweep wall halves vs FTOK=32. Last CTA computes
// the aux loss first (overlapped with other CTAs' sweeps).
__global__ __launch_bounds__(256) void fixup_kernel(
    const float* __restrict__ x, const float* __restrict__ w,
    float* __restrict__ out, int T, int S, int B)
{
    __shared__ float4 ws4[8 * 66];
    __shared__ float4 xs4[FTOK * 9];
    __shared__ float  lgs[FTOK][68];
    __shared__ float  red[256];

    const int tid = threadIdx.x;
    const int e   = tid & 63;
    const int tp  = tid >> 6;             // 0..3 -> tokens 4tp..4tp+3
    const int nflag = g_flag_cnt;

    // ---- fused aux loss (last CTA only; ~3us, hidden under other CTAs) ----
    if (blockIdx.x == FGRID - 1) {
        int b = tid >> 6, ee = tid & 63;
        float ps = 0.f, cs = 0.f;
        int blk0 = b * (NBLK / 4);
        for (int blk = blk0; blk < blk0 + NBLK / 4; blk++) {
            ps += g_pi_part[blk * NEXP + ee];
            cs += g_cnt_part[blk * NEXP + ee];
        }
        float pi = ps / (float)S;
        float fi = cs * ((float)NEXP / (float)(S * KTOP));
        red[tid] = pi * fi;
        __syncthreads();
        for (int s = 128; s > 0; s >>= 1) {
            if (tid < s) red[tid] += red[tid + s];
            __syncthreads();
        }
        if (tid == 0)
            out[(size_t)2 * T * KTOP] = red[0] * 0.01f / (float)B;
        __syncthreads();
    }

    const int wr0 = tid >> 3,        wq = tid & 7;
    const int wr1 = (tid + 256) >> 3;
    const int xt  = tid >> 3,        xq = tid & 7;   // tid<128: 16 tok x 8 segs

    for (int base = blockIdx.x * FTOK; base < nflag; base += FGRID * FTOK) {
        float acc[4];
#pragma unroll
        for (int u = 0; u < 4; u++) acc[u] = 0.f;

        int fi = 0;
        if (tid < 128)
            fi = (base + xt < nflag) ? g_flag_idx[base + xt] : g_flag_idx[base];

        float4 pw0 = *(const float4*)(w + (size_t)wr0 * HDIM + wq * 4);
        float4 pw1 = *(const float4*)(w + (size_t)wr1 * HDIM + wq * 4);
        float4 px  = (tid < 128) ? *(const float4*)(x + (size_t)fi * HDIM + xq * 4)
                                 : make_float4(0.f, 0.f, 0.f, 0.f);

        for (int c = 0; c < 64; c++) {
            ws4[wq * 66 + wr0] = pw0;
            ws4[wq * 66 + wr1] = pw1;
            if (tid < 128) xs4[xt * 9 + xq] = px;
            __syncthreads();

            if (c < 63) {
                pw0 = *(const float4*)(w + (size_t)wr0 * HDIM + (c + 1) * 32 + wq * 4);
                pw1 = *(const float4*)(w + (size_t)wr1 * HDIM + (c + 1) * 32 + wq * 4);
                if (tid < 128)
                    px = *(const float4*)(x + (size_t)fi * HDIM + (c + 1) * 32 + xq * 4);
            }
#pragma unroll
            for (int kq = 0; kq < 8; kq++) {
                float4 wv = ws4[kq * 66 + e];
#pragma unroll
                for (int u = 0; u < 4; u++) {
                    float4 xv = xs4[(4 * tp + u) * 9 + kq];
                    acc[u] = fmaf(xv.x, wv.x, acc[u]);
                    acc[u] = fmaf(xv.y, wv.y, acc[u]);
                    acc[u] = fmaf(xv.z, wv.z, acc[u]);
                    acc[u] = fmaf(xv.w, wv.w, acc[u]);
                }
            }
            __syncthreads();
        }

#pragma unroll
        for (int u = 0; u < 4; u++) lgs[4 * tp + u][e] = acc[u];
        __syncthreads();

        if (tid < FTOK && base + tid < nflag) {
            int t = g_flag_idx[base + tid];
            float sc[NEXP];
            float mx = -1e30f;
#pragma unroll
            for (int j = 0; j < NEXP; j++) { sc[j] = lgs[tid][j]; mx = fmaxf(mx, sc[j]); }
            float sum = 0.f;
#pragma unroll
            for (int j = 0; j < NEXP; j++) { sc[j] = __expf(sc[j] - mx); sum += sc[j]; }
            float inv = 1.f / sum;
#pragma unroll
            for (int j = 0; j < NEXP; j++) sc[j] *= inv;

            float wsel[KTOP]; int isel[KTOP]; float wsum = 0.f;
#pragma unroll
            for (int j = 0; j < KTOP; j++) {
                float bv = -1.f; int bi = 0;
#pragma unroll
                for (int e2 = 0; e2 < NEXP; e2++) if (sc[e2] > bv) { bv = sc[e2]; bi = e2; }
                wsel[j] = bv; isel[j] = bi; wsum += bv;
                sc[bi] = -1.f;
            }
            float rn = 1.f / (wsum + 1e-20f);
#pragma unroll
            for (int j = 0; j < KTOP; j++) {
                out[(size_t)t * KTOP + j] = (float)isel[j];
                out[(size_t)T * KTOP + (size_t)t * KTOP + j] = wsel[j] * rn;
            }
        }
        __syncthreads();
    }
}

extern "C" void kernel_launch(void* const* d_in, const int* in_sizes, int n_in,
                              void* d_out, int out_size)
{
    const float* x = (const float*)d_in[0];
    const float* w = (const float*)d_in[1];
    float* out = (float*)d_out;

    int Hrt = in_sizes[1] / NEXP;    // 2048
    int T   = in_sizes[0] / Hrt;     // 16384
    int B   = 4;
    int S   = T / B;                 // 4096

    size_t smem_bytes = 2 * STG_HALVES * sizeof(__half);   // 20480
    cudaFuncSetAttribute(gate_kernel, cudaFuncAttributeMaxDynamicSharedMemorySize,
                         (int)smem_bytes);

    prep_w<<<64, 256>>>(w);
    gate_kernel<<<T / BM, NTHR, smem_bytes>>>(x, w, out, T, S);
    fixup_kernel<<<FGRID, 256>>>(x, w, out, T, S, B);
}